// round 13
// baseline (speedup 1.0000x reference)
#include <cuda_runtime.h>
#include <cuda_bf16.h>
#include <cstdint>

#define BATCH 4
#define CCH   512
#define ICH   256
#define NPIX  4096
#define BNEPS 1e-5f

// ---------------------------------------------------------------------------
// Scratch (device globals)
// ---------------------------------------------------------------------------
static __device__ uint16_t g_xb  [(size_t)BATCH * CCH * NPIX];   // xA bf16
static __device__ uint16_t g_wkqv[768 * CCH];                    // [wk;wq;wv] bf16
static __device__ float    g_bkqv[768];
static __device__ uint16_t g_kqv [(size_t)BATCH * 768 * NPIX];   // k|q|v bf16
static __device__ uint16_t g_w2b [ICH * ICH];                    // diag(sc1)*wwg bf16
static __device__ uint16_t g_w3b [CCH * ICH];                    // wout bf16
static __device__ uint16_t g_w5  [CCH * ICH];                    // wout*diag(sc1)*wwg bf16
static __device__ float    g_shB [CCH];                          // folded final shift
static __device__ uint16_t g_E   [(size_t)BATCH * NPIX * NPIX];  // exp(S) bf16
static __device__ float    g_Zp  [(size_t)BATCH * 32 * NPIX];    // per-CTA row sums
static __device__ float    g_invZ[(size_t)BATCH * NPIX];
static __device__ uint16_t g_kz  [(size_t)BATCH * ICH * NPIX];   // k * invZ bf16
static __device__ uint16_t g_avb [(size_t)BATCH * ICH * NPIX];
static __device__ float g_sc2[CCH];

// ---------------------------------------------------------------------------
// Helpers
// ---------------------------------------------------------------------------
__device__ __forceinline__ uint32_t cvt2(float a, float b) {
    __nv_bfloat162 h = __floats2bfloat162_rn(a, b);
    return *(uint32_t*)&h;
}
__device__ __forceinline__ uint16_t f2b(float x) {
    __nv_bfloat16 b = __float2bfloat16_rn(x);
    return *(uint16_t*)&b;
}
__device__ __forceinline__ void ldsm4(uint32_t* r, uint32_t addr) {
    asm volatile("ldmatrix.sync.aligned.m8n8.x4.shared.b16 {%0,%1,%2,%3}, [%4];"
                 : "=r"(r[0]), "=r"(r[1]), "=r"(r[2]), "=r"(r[3]) : "r"(addr));
}
__device__ __forceinline__ void ldsm4t(uint32_t* r, uint32_t addr) {
    asm volatile("ldmatrix.sync.aligned.m8n8.x4.trans.shared.b16 {%0,%1,%2,%3}, [%4];"
                 : "=r"(r[0]), "=r"(r[1]), "=r"(r[2]), "=r"(r[3]) : "r"(addr));
}
__device__ __forceinline__ void mma16816(float* c, const uint32_t* a,
                                         uint32_t b0, uint32_t b1) {
    asm volatile(
        "mma.sync.aligned.m16n8k16.row.col.f32.bf16.bf16.f32 "
        "{%0,%1,%2,%3}, {%4,%5,%6,%7}, {%8,%9}, {%0,%1,%2,%3};"
        : "+f"(c[0]), "+f"(c[1]), "+f"(c[2]), "+f"(c[3])
        : "r"(a[0]), "r"(a[1]), "r"(a[2]), "r"(a[3]), "r"(b0), "r"(b1));
}
__device__ __forceinline__ void cpa16(uint32_t dst, const void* src) {
    asm volatile("cp.async.cg.shared.global [%0], [%1], 16;" :: "r"(dst), "l"(src));
}

// ---------------------------------------------------------------------------
// Prep kernels
// ---------------------------------------------------------------------------
__global__ void prep_weights(const float* __restrict__ wk, const float* __restrict__ bk,
                             const float* __restrict__ wv, const float* __restrict__ bv,
                             const float* __restrict__ wq, const float* __restrict__ bq,
                             const float* __restrict__ wwg,
                             const float* __restrict__ g1, const float* __restrict__ v1,
                             const float* __restrict__ wout,
                             const float* __restrict__ g2, const float* __restrict__ v2)
{
    int i = blockIdx.x * blockDim.x + threadIdx.x;
    int tot = blockDim.x * gridDim.x;
    for (int idx = i; idx < 768 * CCH; idx += tot) {
        int r = idx / CCH, c = idx % CCH;
        float v = (r < 256) ? wk[r * CCH + c]
                : (r < 512) ? wq[(r - 256) * CCH + c]
                            : wv[(r - 512) * CCH + c];
        g_wkqv[idx] = f2b(v);
    }
    // g_w2b = diag(sc1) * wwg
    for (int idx = i; idx < ICH * ICH; idx += tot) {
        int o = idx / ICH;
        float s = g1[o] * rsqrtf(v1[o] + BNEPS);
        g_w2b[idx] = f2b(wwg[idx] * s);
    }
    for (int idx = i; idx < CCH * ICH; idx += tot) g_w3b[idx] = f2b(wout[idx]);
    if (i < 768) g_bkqv[i] = (i < 256) ? bk[i] : (i < 512) ? bq[i - 256] : bv[i - 512];
    if (i < CCH) g_sc2[i] = g2[i] * rsqrtf(v2[i] + BNEPS);
}

// shB[m] = sc2[m]*( bout[m] + sum_c wout[m,c]*sh1[c] - m2[m] ) + b2[m]
__global__ void prep_shB(const float* __restrict__ wout, const float* __restrict__ bout,
                         const float* __restrict__ g1, const float* __restrict__ b1,
                         const float* __restrict__ m1, const float* __restrict__ v1,
                         const float* __restrict__ g2, const float* __restrict__ b2,
                         const float* __restrict__ m2, const float* __restrict__ v2)
{
    int m = blockIdx.x * blockDim.x + threadIdx.x;
    if (m < CCH) {
        float acc = 0.f;
        for (int c = 0; c < ICH; c++) {
            float s1 = g1[c] * rsqrtf(v1[c] + BNEPS);
            float sh1 = b1[c] - m1[c] * s1;
            acc += wout[m * ICH + c] * sh1;
        }
        float s2 = g2[m] * rsqrtf(v2[m] + BNEPS);
        g_shB[m] = s2 * (bout[m] + acc - m2[m]) + b2[m];
    }
}

// widened: 8 elems per thread, 16B store
__global__ void cvt_x(const float* __restrict__ x, uint16_t* __restrict__ o)
{
    size_t i = (size_t)blockIdx.x * blockDim.x + threadIdx.x;
    const size_t n8 = (size_t)BATCH * CCH * NPIX / 8;
    if (i < n8) {
        float4 v0 = ((const float4*)x)[2 * i];
        float4 v1 = ((const float4*)x)[2 * i + 1];
        ((uint4*)o)[i] = make_uint4(cvt2(v0.x, v0.y), cvt2(v0.z, v0.w),
                                    cvt2(v1.x, v1.y), cvt2(v1.z, v1.w));
    }
}

__global__ void zreduce(void)
{
    int idx = blockIdx.x * blockDim.x + threadIdx.x;
    if (idx < BATCH * NPIX) {
        int b = idx >> 12, n = idx & 4095;
        float s = 0.f;
        const float* p = g_Zp + ((size_t)b << 5 << 12) + n;
#pragma unroll
        for (int j = 0; j < 32; j++) s += p[(size_t)j << 12];
        g_invZ[idx] = 1.0f / s;
    }
}

__global__ void kscale(void)
{
    size_t i = (size_t)blockIdx.x * blockDim.x + threadIdx.x;
    const size_t tot = (size_t)BATCH * ICH * NPIX / 2;
    if (i < tot) {
        size_t pair = i;
        int n2 = (int)(pair & (NPIX / 2 - 1));
        size_t bc = pair >> 11;
        int b = (int)(bc >> 8);
        uint32_t kv = *(const uint32_t*)(g_kqv + (bc >> 8) * ((size_t)768 * NPIX)
                                         + (bc & 255) * (size_t)NPIX + n2 * 2);
        __nv_bfloat162 kb = *(__nv_bfloat162*)&kv;
        const float2 iz = *(const float2*)(g_invZ + (size_t)b * NPIX + n2 * 2);
        *(uint32_t*)(g_kz + pair * 2) = cvt2(__bfloat162float(kb.x) * iz.x,
                                             __bfloat162float(kb.y) * iz.y);
    }
}

// ---------------------------------------------------------------------------
// bf16 HMMA GEMM (R11 core, verbatim). CTA 128x128xBK32, 256 thr = 8 warps
// (4m x 2n), warp 32x64. 4-stage cp.async pipeline. TRA: A stored [K,M].
// EPI: 0 +bias[m] -> bf16 | 4 *scale+shift+resid,relu -> fp32
//      5 exp(acc) -> bf16 + per-CTA row sums
// ---------------------------------------------------------------------------
template<bool TRA, int EPI>
__global__ __launch_bounds__(256, 2)
void hmma_gemm(const uint16_t* __restrict__ A, const uint16_t* __restrict__ B,
               void* __restrict__ Cv, int M, int N, int K,
               size_t strA, size_t strB, size_t strC,
               const float* __restrict__ bias,
               const float* __restrict__ scale, const float* __restrict__ shift,
               const float* __restrict__ resid, size_t sR,
               float* __restrict__ zpart)
{
    constexpr int ST  = 4;
    constexpr int ASZ = TRA ? 32 * 136 : 128 * 40;
    constexpr int BSZ = 32 * 136;
    extern __shared__ __align__(16) uint16_t sh[];
    uint16_t* smA = sh;
    uint16_t* smB = sh + ST * ASZ;

    const int tid = threadIdx.x, lane = tid & 31, wid = tid >> 5;
    const int wm = wid & 3, wn = wid >> 2;
    const int bz = blockIdx.z, bm = blockIdx.y * 128, bn = blockIdx.x * 128;

    const uint16_t* aBase;
    uint32_t aSm;
    size_t aStep;
    if constexpr (TRA) {
        aBase = A + (size_t)bz * strA + (size_t)(tid >> 3) * M + bm + (tid & 7) * 8;
        aSm   = (tid >> 3) * 136 + (tid & 7) * 8;
        aStep = (size_t)32 * M;
    } else {
        aBase = A + (size_t)bz * strA + (size_t)(bm + (tid >> 1)) * K + (tid & 1) * 16;
        aSm   = (tid >> 1) * 40 + (tid & 1) * 16;
        aStep = 32;
    }
    const uint16_t* bBase = B + (size_t)bz * strB + (size_t)(tid >> 3) * N + bn + (tid & 7) * 8;
    const uint32_t  bSm   = (tid >> 3) * 136 + (tid & 7) * 8;
    const size_t    bStep = (size_t)32 * N;

    float acc[2][8][4] = {};

    auto loadStage = [&](int ch, int s) {
        const uint16_t* ap = aBase + (size_t)ch * aStep;
        const uint16_t* bp = bBase + (size_t)ch * bStep;
        uint32_t ad = (uint32_t)__cvta_generic_to_shared(smA + s * ASZ + aSm);
        uint32_t bd = (uint32_t)__cvta_generic_to_shared(smB + s * BSZ + bSm);
        if constexpr (TRA) {
#pragma unroll
            for (int j = 0; j < 2; j++) cpa16(ad + j * 128, ap + j * 64);
        } else {
#pragma unroll
            for (int j = 0; j < 2; j++) cpa16(ad + j * 16, ap + j * 8);
        }
#pragma unroll
        for (int j = 0; j < 2; j++) cpa16(bd + j * 128, bp + j * 64);
    };

    uint32_t aL;
    if constexpr (TRA) aL = (lane & 15) * 136 + wm * 32 + (lane >> 4) * 8;
    else               aL = (wm * 32 + (lane & 15)) * 40 + (lane >> 4) * 8;
    const uint32_t bL = (lane & 15) * 136 + wn * 64 + (lane >> 4) * 8;

    auto compute = [&](int s) {
        const uint16_t* pA = smA + s * ASZ;
        const uint16_t* pB = smB + s * BSZ;
#pragma unroll
        for (int ks = 0; ks < 2; ks++) {
            uint32_t af[2][4], bf[4][4];
#pragma unroll
            for (int mt = 0; mt < 2; mt++) {
                if constexpr (TRA) {
                    uint32_t r[4];
                    ldsm4t(r, (uint32_t)__cvta_generic_to_shared(
                        pA + aL + ks * 16 * 136 + mt * 16));
                    af[mt][0] = r[0]; af[mt][1] = r[2];
                    af[mt][2] = r[1]; af[mt][3] = r[3];
                } else {
                    ldsm4(af[mt], (uint32_t)__cvta_generic_to_shared(
                        pA + aL + mt * 16 * 40 + ks * 16));
                }
            }
#pragma unroll
            for (int pr = 0; pr < 4; pr++) {
                ldsm4t(bf[pr], (uint32_t)__cvta_generic_to_shared(
                    pB + bL + ks * 16 * 136 + pr * 16));
            }
#pragma unroll
            for (int mt = 0; mt < 2; mt++)
#pragma unroll
                for (int nt = 0; nt < 8; nt++)
                    mma16816(acc[mt][nt], af[mt],
                             bf[nt >> 1][(nt & 1) * 2], bf[nt >> 1][(nt & 1) * 2 + 1]);
        }
    };

    const int nch = K / 32;
#pragma unroll
    for (int s = 0; s < ST - 1; s++) {
        if (s < nch) loadStage(s, s);
        asm volatile("cp.async.commit_group;" ::: "memory");
    }
    for (int ch = 0; ch < nch; ch++) {
        asm volatile("cp.async.wait_group %0;" :: "n"(ST - 2) : "memory");
        __syncthreads();
        compute(ch & (ST - 1));
        int nx = ch + ST - 1;
        if (nx < nch) loadStage(nx, nx & (ST - 1));
        asm volatile("cp.async.commit_group;" ::: "memory");
    }

    if (EPI == 5) {
        __syncthreads();
        float* srow = (float*)sh;
        if (tid < 128) srow[tid] = 0.f;
        __syncthreads();
        uint16_t* Cb = (uint16_t*)Cv + (size_t)bz * strC;
#pragma unroll
        for (int mt = 0; mt < 2; mt++) {
            const int lr0 = wm * 32 + mt * 16 + (lane >> 2);
            const int lr1 = lr0 + 8;
            float s0 = 0.f, s1 = 0.f;
#pragma unroll
            for (int nt = 0; nt < 8; nt++) {
                const int c = bn + wn * 64 + nt * 8 + (lane & 3) * 2;
                float e00 = __expf(acc[mt][nt][0]);
                float e01 = __expf(acc[mt][nt][1]);
                float e10 = __expf(acc[mt][nt][2]);
                float e11 = __expf(acc[mt][nt][3]);
                *(uint32_t*)&Cb[(size_t)(bm + lr0) * N + c] = cvt2(e00, e01);
                *(uint32_t*)&Cb[(size_t)(bm + lr1) * N + c] = cvt2(e10, e11);
                s0 += e00 + e01;
                s1 += e10 + e11;
            }
            s0 += __shfl_xor_sync(0xFFFFFFFF, s0, 1);
            s0 += __shfl_xor_sync(0xFFFFFFFF, s0, 2);
            s1 += __shfl_xor_sync(0xFFFFFFFF, s1, 1);
            s1 += __shfl_xor_sync(0xFFFFFFFF, s1, 2);
            if ((lane & 3) == 0) {
                atomicAdd(&srow[lr0], s0);
                atomicAdd(&srow[lr1], s1);
            }
        }
        __syncthreads();
        if (tid < 128)
            zpart[((size_t)bz * gridDim.x + blockIdx.x) * M + bm + tid] = srow[tid];
        return;
    }

#pragma unroll
    for (int mt = 0; mt < 2; mt++) {
        const int r0 = bm + wm * 32 + mt * 16 + (lane >> 2);
        const int r1 = r0 + 8;
        float sc0 = 1.f, sh0 = 0.f, sc1 = 1.f, sh1 = 0.f;
        if (EPI == 0) {
            sh0 = bias ? bias[r0] : 0.f;
            sh1 = bias ? bias[r1] : 0.f;
        } else if (EPI == 4) {
            sc0 = scale[r0]; sh0 = shift[r0];
            sc1 = scale[r1]; sh1 = shift[r1];
        }
#pragma unroll
        for (int nt = 0; nt < 8; nt++) {
            const int c = bn + wn * 64 + nt * 8 + (lane & 3) * 2;
            float v00 = acc[mt][nt][0] * sc0 + sh0;
            float v01 = acc[mt][nt][1] * sc0 + sh0;
            float v10 = acc[mt][nt][2] * sc1 + sh1;
            float v11 = acc[mt][nt][3] * sc1 + sh1;
            if (EPI == 0) {
                uint16_t* Cb = (uint16_t*)Cv + (size_t)bz * strC;
                *(uint32_t*)&Cb[(size_t)r0 * N + c] = cvt2(v00, v01);
                *(uint32_t*)&Cb[(size_t)r1 * N + c] = cvt2(v10, v11);
            } else {
                float* Cb = (float*)Cv + (size_t)bz * strC;
                const float* Rb = resid + (size_t)bz * sR;
                float2 q0 = *(const float2*)&Rb[(size_t)r0 * N + c];
                float2 q1 = *(const float2*)&Rb[(size_t)r1 * N + c];
                *(float2*)&Cb[(size_t)r0 * N + c] =
                    make_float2(fmaxf(v00 + q0.x, 0.f), fmaxf(v01 + q0.y, 0.f));
                *(float2*)&Cb[(size_t)r1 * N + c] =
                    make_float2(fmaxf(v10 + q1.x, 0.f), fmaxf(v11 + q1.y, 0.f));
            }
        }
    }
}

// ---------------------------------------------------------------------------
// Launch
// ---------------------------------------------------------------------------
extern "C" void kernel_launch(void* const* d_in, const int* in_sizes, int n_in,
                              void* d_out, int out_size)
{
    const float* xA   = (const float*)d_in[0];
    const float* wk   = (const float*)d_in[1];
    const float* bk   = (const float*)d_in[2];
    const float* wv   = (const float*)d_in[3];
    const float* bv   = (const float*)d_in[4];
    const float* wq   = (const float*)d_in[5];
    const float* bq   = (const float*)d_in[6];
    const float* wwg  = (const float*)d_in[7];
    const float* bn1g = (const float*)d_in[8];
    const float* bn1b = (const float*)d_in[9];
    const float* bn1m = (const float*)d_in[10];
    const float* bn1v = (const float*)d_in[11];
    const float* wout = (const float*)d_in[12];
    const float* bout = (const float*)d_in[13];
    const float* bn2g = (const float*)d_in[14];
    const float* bn2b = (const float*)d_in[15];
    const float* bn2m = (const float*)d_in[16];
    const float* bn2v = (const float*)d_in[17];
    float* out = (float*)d_out;

    const int SMEM_NT = 4 * (128 * 40 + 32 * 136) * 2;  // 75776 B
    const int SMEM_T  = 4 * (32 * 136 + 32 * 136) * 2;  // 69632 B
    cudaFuncSetAttribute(hmma_gemm<false, 0>, cudaFuncAttributeMaxDynamicSharedMemorySize, SMEM_NT);
    cudaFuncSetAttribute(hmma_gemm<false, 4>, cudaFuncAttributeMaxDynamicSharedMemorySize, SMEM_NT);
    cudaFuncSetAttribute(hmma_gemm<true, 5>,  cudaFuncAttributeMaxDynamicSharedMemorySize, SMEM_T);

    uint16_t *pxb, *pwkqv, *pkqv, *pw2, *pw3, *pw5, *pE, *pkz, *pavb;
    float *pbkqv, *pZp, *psc2, *pshB;
    cudaGetSymbolAddress((void**)&pxb,   g_xb);
    cudaGetSymbolAddress((void**)&pwkqv, g_wkqv);
    cudaGetSymbolAddress((void**)&pbkqv, g_bkqv);
    cudaGetSymbolAddress((void**)&pkqv,  g_kqv);
    cudaGetSymbolAddress((void**)&pw2,   g_w2b);
    cudaGetSymbolAddress((void**)&pw3,   g_w3b);
    cudaGetSymbolAddress((void**)&pw5,   g_w5);
    cudaGetSymbolAddress((void**)&pE,    g_E);
    cudaGetSymbolAddress((void**)&pZp,   g_Zp);
    cudaGetSymbolAddress((void**)&pkz,   g_kz);
    cudaGetSymbolAddress((void**)&pavb,  g_avb);
    cudaGetSymbolAddress((void**)&psc2,  g_sc2);
    cudaGetSymbolAddress((void**)&pshB,  g_shB);

    // 0) prep
    prep_weights<<<256, 256>>>(wk, bk, wv, bv, wq, bq, wwg,
                               bn1g, bn1v, wout, bn2g, bn2v);
    prep_shB<<<2, 256>>>(wout, bout, bn1g, bn1b, bn1m, bn1v,
                         bn2g, bn2b, bn2m, bn2v);
    cvt_x<<<(int)(((size_t)BATCH * CCH * NPIX / 8 + 255) / 256), 256>>>(xA, pxb);

    const size_t sX   = (size_t)CCH * NPIX;
    const size_t sIC  = (size_t)ICH * NPIX;
    const size_t sKQV = (size_t)768 * NPIX;
    const size_t sS   = (size_t)NPIX * NPIX;

    // 0b) W5 = wout @ (diag(sc1) wwg)  [512 x 256]
    {
        dim3 grd(ICH / 128, CCH / 128, 1);
        hmma_gemm<false, 0><<<grd, 256, SMEM_NT>>>(pw3, pw2, pw5, CCH, ICH, ICH,
                                                   0, 0, 0, nullptr,
                                                   nullptr, nullptr, nullptr, 0, nullptr);
    }
    // 1) fused projections: kqv[o,n] = Wkqv[o,c] * xb[c,n] + b
    {
        dim3 grd(NPIX / 128, 768 / 128, BATCH);
        hmma_gemm<false, 0><<<grd, 256, SMEM_NT>>>(pwkqv, pxb, pkqv, 768, NPIX, CCH,
                                                   0, sX, sKQV, pbkqv,
                                                   nullptr, nullptr, nullptr, 0, nullptr);
    }
    // 2) E = exp(v^T q), row-sum partials -> Zp
    {
        dim3 grd(NPIX / 128, NPIX / 128, BATCH);
        hmma_gemm<true, 5><<<grd, 256, SMEM_T>>>(pkqv + (size_t)512 * NPIX,
                                                 pkqv + (size_t)256 * NPIX,
                                                 pE, NPIX, NPIX, ICH,
                                                 sKQV, sKQV, sS,
                                                 nullptr, nullptr, nullptr, nullptr, 0, pZp);
    }
    // 3) invZ, k' = k*invZ
    zreduce<<<(BATCH * NPIX + 255) / 256, 256>>>();
    kscale<<<(int)(((size_t)BATCH * ICH * NPIX / 2 + 255) / 256), 256>>>();

    // 4) av = k' @ E
    {
        dim3 grd(NPIX / 128, ICH / 128, BATCH);
        hmma_gemm<false, 0><<<grd, 256, SMEM_NT>>>(pkz, pE, pavb, ICH, NPIX, NPIX,
                                                   sIC, sS, sIC,
                                                   nullptr, nullptr, nullptr, nullptr, 0, nullptr);
    }
    // 5) out = relu(sc2*(W5@av) + shB + xA)
    {
        dim3 grd(NPIX / 128, CCH / 128, BATCH);
        hmma_gemm<false, 4><<<grd, 256, SMEM_NT>>>(pw5, pavb, out, CCH, NPIX, ICH,
                                                   0, sIC, sX,
                                                   nullptr, psc2, pshB, xA, sX, nullptr);
    }
}

// round 14
// speedup vs baseline: 1.1445x; 1.1445x over previous
#include <cuda_runtime.h>
#include <cuda_bf16.h>
#include <cstdint>

#define BATCH 4
#define CCH   512
#define ICH   256
#define NPIX  4096
#define BNEPS 1e-5f

// ---------------------------------------------------------------------------
// Scratch (device globals)
// ---------------------------------------------------------------------------
static __device__ uint16_t g_xb  [(size_t)BATCH * CCH * NPIX];   // xA bf16
static __device__ uint16_t g_wkqv[768 * CCH];                    // [wk;wq;wv] bf16
static __device__ float    g_bkqv[768];
static __device__ uint16_t g_kqv [(size_t)BATCH * 768 * NPIX];   // k|q|v bf16
static __device__ uint16_t g_w2b [ICH * ICH];                    // diag(sc1)*wwg bf16
static __device__ uint16_t g_w3b [CCH * ICH];                    // wout bf16
static __device__ uint16_t g_w5  [CCH * ICH];                    // wout*diag(sc1)*wwg bf16
static __device__ float    g_shB [CCH];                          // folded final shift
static __device__ uint16_t g_E   [(size_t)BATCH * NPIX * NPIX];  // exp(S) bf16
static __device__ float    g_Zp  [(size_t)BATCH * 32 * NPIX];    // per-CTA row sums
static __device__ float    g_invZ[(size_t)BATCH * NPIX];
static __device__ uint16_t g_kz  [(size_t)BATCH * ICH * NPIX];   // k * invZ bf16
static __device__ uint16_t g_avb [(size_t)BATCH * ICH * NPIX];
static __device__ float g_sc2[CCH];

// ---------------------------------------------------------------------------
// Helpers
// ---------------------------------------------------------------------------
__device__ __forceinline__ uint32_t cvt2(float a, float b) {
    __nv_bfloat162 h = __floats2bfloat162_rn(a, b);
    return *(uint32_t*)&h;
}
__device__ __forceinline__ uint16_t f2b(float x) {
    __nv_bfloat16 b = __float2bfloat16_rn(x);
    return *(uint16_t*)&b;
}
__device__ __forceinline__ void ldsm4(uint32_t* r, uint32_t addr) {
    asm volatile("ldmatrix.sync.aligned.m8n8.x4.shared.b16 {%0,%1,%2,%3}, [%4];"
                 : "=r"(r[0]), "=r"(r[1]), "=r"(r[2]), "=r"(r[3]) : "r"(addr));
}
__device__ __forceinline__ void ldsm4t(uint32_t* r, uint32_t addr) {
    asm volatile("ldmatrix.sync.aligned.m8n8.x4.trans.shared.b16 {%0,%1,%2,%3}, [%4];"
                 : "=r"(r[0]), "=r"(r[1]), "=r"(r[2]), "=r"(r[3]) : "r"(addr));
}
__device__ __forceinline__ void mma16816(float* c, const uint32_t* a,
                                         uint32_t b0, uint32_t b1) {
    asm volatile(
        "mma.sync.aligned.m16n8k16.row.col.f32.bf16.bf16.f32 "
        "{%0,%1,%2,%3}, {%4,%5,%6,%7}, {%8,%9}, {%0,%1,%2,%3};"
        : "+f"(c[0]), "+f"(c[1]), "+f"(c[2]), "+f"(c[3])
        : "r"(a[0]), "r"(a[1]), "r"(a[2]), "r"(a[3]), "r"(b0), "r"(b1));
}
__device__ __forceinline__ void cpa16(uint32_t dst, const void* src) {
    asm volatile("cp.async.cg.shared.global [%0], [%1], 16;" :: "r"(dst), "l"(src));
}

// ---------------------------------------------------------------------------
// Prep kernels
// ---------------------------------------------------------------------------
__global__ void prep_weights(const float* __restrict__ wk, const float* __restrict__ bk,
                             const float* __restrict__ wv, const float* __restrict__ bv,
                             const float* __restrict__ wq, const float* __restrict__ bq,
                             const float* __restrict__ wwg,
                             const float* __restrict__ g1, const float* __restrict__ v1,
                             const float* __restrict__ wout,
                             const float* __restrict__ g2, const float* __restrict__ v2)
{
    int i = blockIdx.x * blockDim.x + threadIdx.x;
    int tot = blockDim.x * gridDim.x;
    for (int idx = i; idx < 768 * CCH; idx += tot) {
        int r = idx / CCH, c = idx % CCH;
        float v = (r < 256) ? wk[r * CCH + c]
                : (r < 512) ? wq[(r - 256) * CCH + c]
                            : wv[(r - 512) * CCH + c];
        g_wkqv[idx] = f2b(v);
    }
    // g_w2b = diag(sc1) * wwg
    for (int idx = i; idx < ICH * ICH; idx += tot) {
        int o = idx / ICH;
        float s = g1[o] * rsqrtf(v1[o] + BNEPS);
        g_w2b[idx] = f2b(wwg[idx] * s);
    }
    for (int idx = i; idx < CCH * ICH; idx += tot) g_w3b[idx] = f2b(wout[idx]);
    if (i < 768) g_bkqv[i] = (i < 256) ? bk[i] : (i < 512) ? bq[i - 256] : bv[i - 512];
    if (i < CCH) g_sc2[i] = g2[i] * rsqrtf(v2[i] + BNEPS);
}

// shB[m] = sc2[m]*( bout[m] + sum_c wout[m,c]*sh1[c] - m2[m] ) + b2[m]
// One block per m (coalesced wout row read), block reduction.
__global__ __launch_bounds__(256)
void prep_shB(const float* __restrict__ wout, const float* __restrict__ bout,
              const float* __restrict__ g1, const float* __restrict__ b1,
              const float* __restrict__ m1, const float* __restrict__ v1,
              const float* __restrict__ g2, const float* __restrict__ b2,
              const float* __restrict__ m2, const float* __restrict__ v2)
{
    __shared__ float red[256];
    const int m = blockIdx.x, c = threadIdx.x;
    float s1  = g1[c] * rsqrtf(v1[c] + BNEPS);
    float sh1 = b1[c] - m1[c] * s1;
    red[c] = wout[m * ICH + c] * sh1;
    __syncthreads();
#pragma unroll
    for (int s = 128; s > 0; s >>= 1) {
        if (c < s) red[c] += red[c + s];
        __syncthreads();
    }
    if (c == 0) {
        float s2v = g2[m] * rsqrtf(v2[m] + BNEPS);
        g_shB[m] = s2v * (bout[m] + red[0] - m2[m]) + b2[m];
    }
}

// widened: 8 elems per thread, 16B store
__global__ void cvt_x(const float* __restrict__ x, uint16_t* __restrict__ o)
{
    size_t i = (size_t)blockIdx.x * blockDim.x + threadIdx.x;
    const size_t n8 = (size_t)BATCH * CCH * NPIX / 8;
    if (i < n8) {
        float4 v0 = ((const float4*)x)[2 * i];
        float4 v1 = ((const float4*)x)[2 * i + 1];
        ((uint4*)o)[i] = make_uint4(cvt2(v0.x, v0.y), cvt2(v0.z, v0.w),
                                    cvt2(v1.x, v1.y), cvt2(v1.z, v1.w));
    }
}

__global__ void zreduce(void)
{
    int idx = blockIdx.x * blockDim.x + threadIdx.x;
    if (idx < BATCH * NPIX) {
        int b = idx >> 12, n = idx & 4095;
        float s = 0.f;
        const float* p = g_Zp + ((size_t)b << 5 << 12) + n;
#pragma unroll
        for (int j = 0; j < 32; j++) s += p[(size_t)j << 12];
        g_invZ[idx] = 1.0f / s;
    }
}

__global__ void kscale(void)
{
    size_t i = (size_t)blockIdx.x * blockDim.x + threadIdx.x;
    const size_t tot = (size_t)BATCH * ICH * NPIX / 2;
    if (i < tot) {
        size_t pair = i;
        int n2 = (int)(pair & (NPIX / 2 - 1));
        size_t bc = pair >> 11;
        int b = (int)(bc >> 8);
        uint32_t kv = *(const uint32_t*)(g_kqv + (bc >> 8) * ((size_t)768 * NPIX)
                                         + (bc & 255) * (size_t)NPIX + n2 * 2);
        __nv_bfloat162 kb = *(__nv_bfloat162*)&kv;
        const float2 iz = *(const float2*)(g_invZ + (size_t)b * NPIX + n2 * 2);
        *(uint32_t*)(g_kz + pair * 2) = cvt2(__bfloat162float(kb.x) * iz.x,
                                             __bfloat162float(kb.y) * iz.y);
    }
}

// ---------------------------------------------------------------------------
// bf16 HMMA GEMM (R11 core, verbatim). CTA 128x128xBK32, 256 thr = 8 warps
// (4m x 2n), warp 32x64. 4-stage cp.async pipeline. TRA: A stored [K,M].
// EPI: 0 +bias[m] -> bf16 | 4 *scale+shift+resid,relu -> fp32
//      5 exp(acc) -> bf16 + per-CTA row sums
// ---------------------------------------------------------------------------
template<bool TRA, int EPI>
__global__ __launch_bounds__(256, 2)
void hmma_gemm(const uint16_t* __restrict__ A, const uint16_t* __restrict__ B,
               void* __restrict__ Cv, int M, int N, int K,
               size_t strA, size_t strB, size_t strC,
               const float* __restrict__ bias,
               const float* __restrict__ scale, const float* __restrict__ shift,
               const float* __restrict__ resid, size_t sR,
               float* __restrict__ zpart)
{
    constexpr int ST  = 4;
    constexpr int ASZ = TRA ? 32 * 136 : 128 * 40;
    constexpr int BSZ = 32 * 136;
    extern __shared__ __align__(16) uint16_t sh[];
    uint16_t* smA = sh;
    uint16_t* smB = sh + ST * ASZ;

    const int tid = threadIdx.x, lane = tid & 31, wid = tid >> 5;
    const int wm = wid & 3, wn = wid >> 2;
    const int bz = blockIdx.z, bm = blockIdx.y * 128, bn = blockIdx.x * 128;

    const uint16_t* aBase;
    uint32_t aSm;
    size_t aStep;
    if constexpr (TRA) {
        aBase = A + (size_t)bz * strA + (size_t)(tid >> 3) * M + bm + (tid & 7) * 8;
        aSm   = (tid >> 3) * 136 + (tid & 7) * 8;
        aStep = (size_t)32 * M;
    } else {
        aBase = A + (size_t)bz * strA + (size_t)(bm + (tid >> 1)) * K + (tid & 1) * 16;
        aSm   = (tid >> 1) * 40 + (tid & 1) * 16;
        aStep = 32;
    }
    const uint16_t* bBase = B + (size_t)bz * strB + (size_t)(tid >> 3) * N + bn + (tid & 7) * 8;
    const uint32_t  bSm   = (tid >> 3) * 136 + (tid & 7) * 8;
    const size_t    bStep = (size_t)32 * N;

    float acc[2][8][4] = {};

    auto loadStage = [&](int ch, int s) {
        const uint16_t* ap = aBase + (size_t)ch * aStep;
        const uint16_t* bp = bBase + (size_t)ch * bStep;
        uint32_t ad = (uint32_t)__cvta_generic_to_shared(smA + s * ASZ + aSm);
        uint32_t bd = (uint32_t)__cvta_generic_to_shared(smB + s * BSZ + bSm);
        if constexpr (TRA) {
#pragma unroll
            for (int j = 0; j < 2; j++) cpa16(ad + j * 128, ap + j * 64);
        } else {
#pragma unroll
            for (int j = 0; j < 2; j++) cpa16(ad + j * 16, ap + j * 8);
        }
#pragma unroll
        for (int j = 0; j < 2; j++) cpa16(bd + j * 128, bp + j * 64);
    };

    uint32_t aL;
    if constexpr (TRA) aL = (lane & 15) * 136 + wm * 32 + (lane >> 4) * 8;
    else               aL = (wm * 32 + (lane & 15)) * 40 + (lane >> 4) * 8;
    const uint32_t bL = (lane & 15) * 136 + wn * 64 + (lane >> 4) * 8;

    auto compute = [&](int s) {
        const uint16_t* pA = smA + s * ASZ;
        const uint16_t* pB = smB + s * BSZ;
#pragma unroll
        for (int ks = 0; ks < 2; ks++) {
            uint32_t af[2][4], bf[4][4];
#pragma unroll
            for (int mt = 0; mt < 2; mt++) {
                if constexpr (TRA) {
                    uint32_t r[4];
                    ldsm4t(r, (uint32_t)__cvta_generic_to_shared(
                        pA + aL + ks * 16 * 136 + mt * 16));
                    af[mt][0] = r[0]; af[mt][1] = r[2];
                    af[mt][2] = r[1]; af[mt][3] = r[3];
                } else {
                    ldsm4(af[mt], (uint32_t)__cvta_generic_to_shared(
                        pA + aL + mt * 16 * 40 + ks * 16));
                }
            }
#pragma unroll
            for (int pr = 0; pr < 4; pr++) {
                ldsm4t(bf[pr], (uint32_t)__cvta_generic_to_shared(
                    pB + bL + ks * 16 * 136 + pr * 16));
            }
#pragma unroll
            for (int mt = 0; mt < 2; mt++)
#pragma unroll
                for (int nt = 0; nt < 8; nt++)
                    mma16816(acc[mt][nt], af[mt],
                             bf[nt >> 1][(nt & 1) * 2], bf[nt >> 1][(nt & 1) * 2 + 1]);
        }
    };

    const int nch = K / 32;
#pragma unroll
    for (int s = 0; s < ST - 1; s++) {
        if (s < nch) loadStage(s, s);
        asm volatile("cp.async.commit_group;" ::: "memory");
    }
    for (int ch = 0; ch < nch; ch++) {
        asm volatile("cp.async.wait_group %0;" :: "n"(ST - 2) : "memory");
        __syncthreads();
        compute(ch & (ST - 1));
        int nx = ch + ST - 1;
        if (nx < nch) loadStage(nx, nx & (ST - 1));
        asm volatile("cp.async.commit_group;" ::: "memory");
    }

    if (EPI == 5) {
        __syncthreads();
        float* srow = (float*)sh;
        if (tid < 128) srow[tid] = 0.f;
        __syncthreads();
        uint16_t* Cb = (uint16_t*)Cv + (size_t)bz * strC;
#pragma unroll
        for (int mt = 0; mt < 2; mt++) {
            const int lr0 = wm * 32 + mt * 16 + (lane >> 2);
            const int lr1 = lr0 + 8;
            float s0 = 0.f, s1 = 0.f;
#pragma unroll
            for (int nt = 0; nt < 8; nt++) {
                const int c = bn + wn * 64 + nt * 8 + (lane & 3) * 2;
                float e00 = __expf(acc[mt][nt][0]);
                float e01 = __expf(acc[mt][nt][1]);
                float e10 = __expf(acc[mt][nt][2]);
                float e11 = __expf(acc[mt][nt][3]);
                *(uint32_t*)&Cb[(size_t)(bm + lr0) * N + c] = cvt2(e00, e01);
                *(uint32_t*)&Cb[(size_t)(bm + lr1) * N + c] = cvt2(e10, e11);
                s0 += e00 + e01;
                s1 += e10 + e11;
            }
            s0 += __shfl_xor_sync(0xFFFFFFFF, s0, 1);
            s0 += __shfl_xor_sync(0xFFFFFFFF, s0, 2);
            s1 += __shfl_xor_sync(0xFFFFFFFF, s1, 1);
            s1 += __shfl_xor_sync(0xFFFFFFFF, s1, 2);
            if ((lane & 3) == 0) {
                atomicAdd(&srow[lr0], s0);
                atomicAdd(&srow[lr1], s1);
            }
        }
        __syncthreads();
        if (tid < 128)
            zpart[((size_t)bz * gridDim.x + blockIdx.x) * M + bm + tid] = srow[tid];
        return;
    }

#pragma unroll
    for (int mt = 0; mt < 2; mt++) {
        const int r0 = bm + wm * 32 + mt * 16 + (lane >> 2);
        const int r1 = r0 + 8;
        float sc0 = 1.f, sh0 = 0.f, sc1 = 1.f, sh1 = 0.f;
        if (EPI == 0) {
            sh0 = bias ? bias[r0] : 0.f;
            sh1 = bias ? bias[r1] : 0.f;
        } else if (EPI == 4) {
            sc0 = scale[r0]; sh0 = shift[r0];
            sc1 = scale[r1]; sh1 = shift[r1];
        }
#pragma unroll
        for (int nt = 0; nt < 8; nt++) {
            const int c = bn + wn * 64 + nt * 8 + (lane & 3) * 2;
            float v00 = acc[mt][nt][0] * sc0 + sh0;
            float v01 = acc[mt][nt][1] * sc0 + sh0;
            float v10 = acc[mt][nt][2] * sc1 + sh1;
            float v11 = acc[mt][nt][3] * sc1 + sh1;
            if (EPI == 0) {
                uint16_t* Cb = (uint16_t*)Cv + (size_t)bz * strC;
                *(uint32_t*)&Cb[(size_t)r0 * N + c] = cvt2(v00, v01);
                *(uint32_t*)&Cb[(size_t)r1 * N + c] = cvt2(v10, v11);
            } else {
                float* Cb = (float*)Cv + (size_t)bz * strC;
                const float* Rb = resid + (size_t)bz * sR;
                float2 q0 = *(const float2*)&Rb[(size_t)r0 * N + c];
                float2 q1 = *(const float2*)&Rb[(size_t)r1 * N + c];
                *(float2*)&Cb[(size_t)r0 * N + c] =
                    make_float2(fmaxf(v00 + q0.x, 0.f), fmaxf(v01 + q0.y, 0.f));
                *(float2*)&Cb[(size_t)r1 * N + c] =
                    make_float2(fmaxf(v10 + q1.x, 0.f), fmaxf(v11 + q1.y, 0.f));
            }
        }
    }
}

// ---------------------------------------------------------------------------
// Launch — fork-join: W5 chain runs on a side stream, overlapped with the
// main path, joined before the final GEMM.
// ---------------------------------------------------------------------------
extern "C" void kernel_launch(void* const* d_in, const int* in_sizes, int n_in,
                              void* d_out, int out_size)
{
    const float* xA   = (const float*)d_in[0];
    const float* wk   = (const float*)d_in[1];
    const float* bk   = (const float*)d_in[2];
    const float* wv   = (const float*)d_in[3];
    const float* bv   = (const float*)d_in[4];
    const float* wq   = (const float*)d_in[5];
    const float* bq   = (const float*)d_in[6];
    const float* wwg  = (const float*)d_in[7];
    const float* bn1g = (const float*)d_in[8];
    const float* bn1b = (const float*)d_in[9];
    const float* bn1m = (const float*)d_in[10];
    const float* bn1v = (const float*)d_in[11];
    const float* wout = (const float*)d_in[12];
    const float* bout = (const float*)d_in[13];
    const float* bn2g = (const float*)d_in[14];
    const float* bn2b = (const float*)d_in[15];
    const float* bn2m = (const float*)d_in[16];
    const float* bn2v = (const float*)d_in[17];
    float* out = (float*)d_out;

    const int SMEM_NT = 4 * (128 * 40 + 32 * 136) * 2;  // 75776 B
    const int SMEM_T  = 4 * (32 * 136 + 32 * 136) * 2;  // 69632 B
    cudaFuncSetAttribute(hmma_gemm<false, 0>, cudaFuncAttributeMaxDynamicSharedMemorySize, SMEM_NT);
    cudaFuncSetAttribute(hmma_gemm<false, 4>, cudaFuncAttributeMaxDynamicSharedMemorySize, SMEM_NT);
    cudaFuncSetAttribute(hmma_gemm<true, 5>,  cudaFuncAttributeMaxDynamicSharedMemorySize, SMEM_T);

    uint16_t *pxb, *pwkqv, *pkqv, *pw2, *pw3, *pw5, *pE, *pkz, *pavb;
    float *pbkqv, *pZp, *psc2, *pshB;
    cudaGetSymbolAddress((void**)&pxb,   g_xb);
    cudaGetSymbolAddress((void**)&pwkqv, g_wkqv);
    cudaGetSymbolAddress((void**)&pbkqv, g_bkqv);
    cudaGetSymbolAddress((void**)&pkqv,  g_kqv);
    cudaGetSymbolAddress((void**)&pw2,   g_w2b);
    cudaGetSymbolAddress((void**)&pw3,   g_w3b);
    cudaGetSymbolAddress((void**)&pw5,   g_w5);
    cudaGetSymbolAddress((void**)&pE,    g_E);
    cudaGetSymbolAddress((void**)&pZp,   g_Zp);
    cudaGetSymbolAddress((void**)&pkz,   g_kz);
    cudaGetSymbolAddress((void**)&pavb,  g_avb);
    cudaGetSymbolAddress((void**)&psc2,  g_sc2);
    cudaGetSymbolAddress((void**)&pshB,  g_shB);

    // side stream + events (host-side resources, created per call; not device mem)
    cudaStream_t s2;
    cudaEvent_t ev0, ev1;
    cudaStreamCreateWithFlags(&s2, cudaStreamNonBlocking);
    cudaEventCreateWithFlags(&ev0, cudaEventDisableTiming);
    cudaEventCreateWithFlags(&ev1, cudaEventDisableTiming);

    const size_t sX   = (size_t)CCH * NPIX;
    const size_t sIC  = (size_t)ICH * NPIX;
    const size_t sKQV = (size_t)768 * NPIX;
    const size_t sS   = (size_t)NPIX * NPIX;

    // 0) prep (main stream)
    prep_weights<<<256, 256>>>(wk, bk, wv, bv, wq, bq, wwg,
                               bn1g, bn1v, wout, bn2g, bn2v);
    cudaEventRecord(ev0, 0);

    // --- side branch: W5 = wout @ (diag(sc1) wwg), shB fold (overlapped)
    cudaStreamWaitEvent(s2, ev0, 0);
    {
        dim3 grd(ICH / 128, CCH / 128, 1);
        hmma_gemm<false, 0><<<grd, 256, SMEM_NT, s2>>>(pw3, pw2, pw5, CCH, ICH, ICH,
                                                       0, 0, 0, nullptr,
                                                       nullptr, nullptr, nullptr, 0, nullptr);
    }
    prep_shB<<<CCH, 256, 0, s2>>>(wout, bout, bn1g, bn1b, bn1m, bn1v,
                                  bn2g, bn2b, bn2m, bn2v);
    cudaEventRecord(ev1, s2);

    // --- main path continues
    cvt_x<<<(int)(((size_t)BATCH * CCH * NPIX / 8 + 255) / 256), 256>>>(xA, pxb);

    // 1) fused projections: kqv[o,n] = Wkqv[o,c] * xb[c,n] + b
    {
        dim3 grd(NPIX / 128, 768 / 128, BATCH);
        hmma_gemm<false, 0><<<grd, 256, SMEM_NT>>>(pwkqv, pxb, pkqv, 768, NPIX, CCH,
                                                   0, sX, sKQV, pbkqv,
                                                   nullptr, nullptr, nullptr, 0, nullptr);
    }
    // 2) E = exp(v^T q), row-sum partials -> Zp
    {
        dim3 grd(NPIX / 128, NPIX / 128, BATCH);
        hmma_gemm<true, 5><<<grd, 256, SMEM_T>>>(pkqv + (size_t)512 * NPIX,
                                                 pkqv + (size_t)256 * NPIX,
                                                 pE, NPIX, NPIX, ICH,
                                                 sKQV, sKQV, sS,
                                                 nullptr, nullptr, nullptr, nullptr, 0, pZp);
    }
    // 3) invZ, k' = k*invZ
    zreduce<<<(BATCH * NPIX + 255) / 256, 256>>>();
    kscale<<<(int)(((size_t)BATCH * ICH * NPIX / 2 + 255) / 256), 256>>>();

    // 4) av = k' @ E
    {
        dim3 grd(NPIX / 128, ICH / 128, BATCH);
        hmma_gemm<false, 0><<<grd, 256, SMEM_NT>>>(pkz, pE, pavb, ICH, NPIX, NPIX,
                                                   sIC, sS, sIC,
                                                   nullptr, nullptr, nullptr, nullptr, 0, nullptr);
    }

    // join side branch before the final GEMM consumes w5/shB
    cudaStreamWaitEvent(0, ev1, 0);

    // 5) out = relu(sc2*(W5@av) + shB + xA)
    {
        dim3 grd(NPIX / 128, CCH / 128, BATCH);
        hmma_gemm<false, 4><<<grd, 256, SMEM_NT>>>(pw5, pavb, out, CCH, NPIX, ICH,
                                                   0, sIC, sX,
                                                   nullptr, psc2, pshB, xA, sX, nullptr);
    }
    // intentionally leak s2/ev0/ev1 (host-side objects; destroying a stream
    // that participated in an ongoing capture is hazardous)
}